// round 15
// baseline (speedup 1.0000x reference)
#include <cuda_runtime.h>
#include <math.h>

// Problem constants
#define LSEQ 1024
#define TIB  16           // i-rows per CTA (2 per thread)
#define TJ   4            // j per tile
#define JS   8            // j-splits
#define JCH  (LSEQ/JS)    // 128 j per CTA
#define NTC  (JCH/TJ)     // 32 tiles per CTA
#define NIB  (LSEQ/TIB)   // 64 i-blocks

#define QS_BH 36                 // padded floats per (b,h) row (conflict-free LDS)
#define QS_JJ (32*QS_BH)         // 1152 floats per jj
#define QBUF  (TJ*QS_JJ)         // 4608 floats per q/v buffer
#define AS_JJ 36
#define AS_TI (TJ*AS_JJ+4)       // 148 floats per ti row
#define ABUF  (TIB*AS_TI)        // 2368 floats per a buffer

#define PB_STRIDE 36             // attn staging row stride: 2 parity groups x 16 + pad
#define PROWS 512                // 16 i x 32 bh

// dynamic smem: max(k1: 3*QBUF+3*ABUF = 20928, k2: 2*QBUF + 512*36 = 27648)
#define SMEM_FLOATS 27648

// Static scratch (allocation-free per harness rules)
__device__ float g_scratch[(size_t)NIB * JS * NTC * 512 * 4];  // p-tilde, 128 MB
__device__ float g_partials[JS * 32768];                       // per-split exp-sums
__device__ float g_opart[(size_t)JS * 32 * 1024 * 32];         // partial PV outputs
__device__ int   g_done[NIB];                                  // per-ib k1 completion count

typedef unsigned long long ull;

__device__ __forceinline__ float2 f2mul(float2 a, float2 b) {
    ull ra = *(ull*)&a, rb = *(ull*)&b, rd;
    asm("mul.rn.f32x2 %0, %1, %2;" : "=l"(rd) : "l"(ra), "l"(rb));
    return *(float2*)&rd;
}
__device__ __forceinline__ float2 f2fma(float2 a, float2 b, float2 c) {
    ull ra = *(ull*)&a, rb = *(ull*)&b, rc = *(ull*)&c, rd;
    asm("fma.rn.f32x2 %0, %1, %2, %3;" : "=l"(rd) : "l"(ra), "l"(rb), "l"(rc));
    return *(float2*)&rd;
}
__device__ __forceinline__ float ex2(float x) {
    float r;
    asm("ex2.approx.f32 %0, %1;" : "=f"(r) : "f"(x));
    return r;
}

#define CPA16(dst_u32, src_ptr) \
    asm volatile("cp.async.cg.shared.global [%0], [%1], 16;" :: "r"(dst_u32), "l"(src_ptr))
#define CPCOMMIT() asm volatile("cp.async.commit_group;" ::: "memory")
#define CPWAIT1()  asm volatile("cp.async.wait_group 1;" ::: "memory")
#define CPWAIT0()  asm volatile("cp.async.wait_group 0;" ::: "memory")

// ============================================================================
// k0: reset per-ib completion counters (only used in attn-only mode; when k3
// runs, k3 itself resets g_done at the end of each launch).
// ============================================================================
__global__ void k0_zero()
{
    if (threadIdx.x < NIB) g_done[threadIdx.x] = 0;
}

// ============================================================================
// Fused launch: bids 0-511 = score chunks (k1), bids 512-1023 = PV chunks (k2).
// ============================================================================
__global__ __launch_bounds__(256, 2)
void k_fused(const float* __restrict__ q,
             const float* __restrict__ k,
             const float* __restrict__ ak,
             const float* __restrict__ v,
             float* __restrict__ attn)
{
    extern __shared__ float sm[];
    const int bid = blockIdx.x;
    const int tid = threadIdx.x;
    const int lane = tid & 31, warp = tid >> 5;
    const int ti = lane >> 2;
    const int bh = warp * 4 + (lane & 3);

    if (bid < NIB * JS) {
        // ==================== SCORE CHUNK (k1, unchanged) ====================
        const int ib  = bid >> 3;
        const int jbs = bid & 7;
        const int b = bh >> 3, h = bh & 7;
        const int i0 = ib * TIB + ti, i1 = i0 + 8;
        const int jbase = jbs * JCH;

        float* q_s = sm;                 // [3][QBUF]
        float* a_s = sm + 3 * QBUF;      // [3][ABUF]
        const unsigned q_su = (unsigned)__cvta_generic_to_shared(q_s);
        const unsigned a_su = (unsigned)__cvta_generic_to_shared(a_s);

        const float SC = 0.17677669529663687f * 1.4426950408889634f;
        float2 kr0[16], kr1[16];
        {
            const float4* kp0 = (const float4*)(k + ((size_t)(b * LSEQ + i0)) * 256 + h * 32);
            const float4* kp1 = (const float4*)(k + ((size_t)(b * LSEQ + i1)) * 256 + h * 32);
            #pragma unroll
            for (int d4 = 0; d4 < 8; d4++) {
                float4 t0 = kp0[d4], t1 = kp1[d4];
                kr0[d4*2]   = make_float2(t0.x * SC, t0.y * SC);
                kr0[d4*2+1] = make_float2(t0.z * SC, t0.w * SC);
                kr1[d4*2]   = make_float2(t1.x * SC, t1.y * SC);
                kr1[d4*2+1] = make_float2(t1.z * SC, t1.w * SC);
            }
        }

        const int qbb = tid >> 6, c4 = tid & 63;
        const unsigned qoffB = (unsigned)(((qbb * 8 + (c4 >> 3)) * QS_BH + (c4 & 7) * 4) * 4);
        const float4* qsrc = (const float4*)q + (size_t)qbb * (LSEQ * 64) + c4;
        const int ati = tid >> 5, ajj = (tid >> 3) & 3, ad4 = tid & 7;
        const unsigned aoff0B = (unsigned)((ati * AS_TI + ajj * AS_JJ + ad4 * 4) * 4);
        const unsigned aoff1B = aoff0B + (unsigned)(8 * AS_TI * 4);
        const float4* asrc0 = (const float4*)ak + ((size_t)(ib * TIB + ati)) * (LSEQ * 8) + ad4;
        const float4* asrc1 = asrc0 + (size_t)8 * (LSEQ * 8);

        #pragma unroll
        for (int t = 0; t < 2; t++) {
            const int j0 = jbase + t * TJ;
            const unsigned qd = q_su + (unsigned)(t * QBUF * 4);
            const unsigned ad = a_su + (unsigned)(t * ABUF * 4);
            #pragma unroll
            for (int r = 0; r < 4; r++)
                CPA16(qd + (unsigned)(r * QS_JJ * 4) + qoffB, qsrc + (size_t)(j0 + r) * 64);
            CPA16(ad + aoff0B, asrc0 + (size_t)(j0 + ajj) * 8);
            CPA16(ad + aoff1B, asrc1 + (size_t)(j0 + ajj) * 8);
            CPCOMMIT();
        }

        float l0 = 0.f, l1 = 0.f;
        float* sbase = g_scratch + (size_t)(ib * JS + jbs) * (NTC * 2048);

        int cur = 0;
        for (int jt = 0; jt < NTC; jt++) {
            CPWAIT1();
            __syncthreads();

            if (jt + 2 < NTC) {
                int sbuf = cur + 2; if (sbuf >= 3) sbuf -= 3;
                const int j0n = jbase + (jt + 2) * TJ;
                const unsigned qd = q_su + (unsigned)(sbuf * QBUF * 4);
                const unsigned ad = a_su + (unsigned)(sbuf * ABUF * 4);
                #pragma unroll
                for (int r = 0; r < 4; r++)
                    CPA16(qd + (unsigned)(r * QS_JJ * 4) + qoffB, qsrc + (size_t)(j0n + r) * 64);
                CPA16(ad + aoff0B, asrc0 + (size_t)(j0n + ajj) * 8);
                CPA16(ad + aoff1B, asrc1 + (size_t)(j0n + ajj) * 8);
                CPCOMMIT();
            }

            const float* qb = q_s + cur * QBUF;
            const float* ab = a_s + cur * ABUF;
            float e4a[TJ], e4b[TJ];

            #pragma unroll
            for (int jj = 0; jj < TJ; jj++) {
                const float* qrow = qb + jj * QS_JJ + bh * QS_BH;
                const float* ar0  = ab + ti * AS_TI + jj * AS_JJ;
                const float* ar1  = ar0 + 8 * AS_TI;
                float2 a00 = make_float2(0.f,0.f), a01 = a00, a10 = a00, a11 = a00;
                #pragma unroll
                for (int d4 = 0; d4 < 8; d4++) {
                    float4 Q  = *(const float4*)(qrow + d4 * 4);
                    float4 A0 = *(const float4*)(ar0  + d4 * 4);
                    float4 A1 = *(const float4*)(ar1  + d4 * 4);
                    float2 qxy = make_float2(Q.x, Q.y), qzw = make_float2(Q.z, Q.w);
                    a00 = f2fma(f2mul(make_float2(A0.x, A0.y), qxy), kr0[d4*2],   a00);
                    a01 = f2fma(f2mul(make_float2(A0.z, A0.w), qzw), kr0[d4*2+1], a01);
                    a10 = f2fma(f2mul(make_float2(A1.x, A1.y), qxy), kr1[d4*2],   a10);
                    a11 = f2fma(f2mul(make_float2(A1.z, A1.w), qzw), kr1[d4*2+1], a11);
                }
                float e0 = ex2((a00.x + a00.y) + (a01.x + a01.y));
                float e1 = ex2((a10.x + a10.y) + (a11.x + a11.y));
                e4a[jj] = e0; l0 += e0;
                e4b[jj] = e1; l1 += e1;
            }

            float* sp = sbase + ((size_t)jt * 512 + tid) * 4;
            __stcs((float4*)sp,          make_float4(e4a[0], e4a[1], e4a[2], e4a[3]));
            __stcs((float4*)(sp + 1024), make_float4(e4b[0], e4b[1], e4b[2], e4b[3]));

            cur = (cur + 1 == 3) ? 0 : cur + 1;
        }

        g_partials[jbs * 32768 + bh * 1024 + i0] = l0;
        g_partials[jbs * 32768 + bh * 1024 + i1] = l1;

        __syncthreads();
        if (tid == 0) {
            __threadfence();
            asm volatile("red.release.gpu.global.add.s32 [%0], 1;"
                         :: "l"(&g_done[ib]) : "memory");
        }

    } else {
        // ==================== PV CHUNK (k2, single-barrier tile loop) ====================
        const int c   = bid - NIB * JS;
        const int ib  = c >> 3;
        const int jbs = c & 7;
        const int i0 = ib * TIB + ti, i1 = i0 + 8;
        const int jbase = jbs * JCH;
        const int row0 = bh * 1024 + i0, row1 = bh * 1024 + i1;

        float* v_s = sm;                 // [2][QBUF]
        float* p_s = sm + 2 * QBUF;      // [512][36]: two 16-col parity groups
        const unsigned v_su = (unsigned)__cvta_generic_to_shared(v_s);

        const int vbb = tid >> 6, c4 = tid & 63;
        const unsigned voffB = (unsigned)(((vbb * 8 + (c4 >> 3)) * QS_BH + (c4 & 7) * 4) * 4);
        const float4* vsrc = (const float4*)v + (size_t)vbb * (LSEQ * 64) + c4;

        // V prologue: tile 0 (buffer 0), before the spin
        {
            #pragma unroll
            for (int r = 0; r < 4; r++)
                CPA16(v_su + (unsigned)(r * QS_JJ * 4) + voffB, vsrc + (size_t)(jbase + r) * 64);
            CPCOMMIT();
        }

        // acquire-spin: all 8 score chunks of this ib must be done
        if (tid == 0) {
            int val;
            do {
                asm volatile("ld.global.acquire.gpu.b32 %0, [%1];"
                             : "=r"(val) : "l"(&g_done[ib]) : "memory");
                if (val < JS) __nanosleep(256);
            } while (val < JS);
        }
        __syncthreads();

        float gl0 = 0.f, gl1 = 0.f;
        #pragma unroll
        for (int t = 0; t < JS; t++) {
            gl0 += g_partials[t * 32768 + row0];
            gl1 += g_partials[t * 32768 + row1];
        }
        const float il0 = 1.0f / gl0, il1 = 1.0f / gl1;

        const float* sbase = g_scratch + (size_t)(ib * JS + jbs) * (NTC * 2048);

        float4 pa = __ldcs((const float4*)(sbase + (size_t)tid * 4));
        float4 pb = __ldcs((const float4*)(sbase + (size_t)tid * 4 + 1024));

        float* ps0 = p_s + (ti * 32 + bh) * PB_STRIDE;
        float* ps1 = p_s + ((ti + 8) * 32 + bh) * PB_STRIDE;
        const int frl = lane >> 2, fk2 = lane & 3;   // flush: row-in-group, float4 col

        float2 acc0[16], acc1[16];
        #pragma unroll
        for (int r = 0; r < 16; r++) { acc0[r] = make_float2(0.f,0.f); acc1[r] = acc0[r]; }

        for (int jt = 0; jt < NTC; jt++) {
            __syncthreads();   // ONE barrier per tile:
                               //  - readers of V buf (jt-1)&1 done -> safe to refill
                               //  - STS of p-group (jt>>2)-1 all visible -> flush safe
                               //  - flush of group (jt>>2)-2 done -> parity reuse safe

            // flush finished p-group (overlaps the cp.async wait below)
            if (attn && (jt & 3) == 0 && jt > 0) {
                const int g = (jt >> 2) - 1;
                const int po = (g & 1) * 16;
                #pragma unroll
                for (int f = 0; f < 8; f++) {
                    const int R  = warp * 64 + f * 8 + frl;   // linear row 0..511
                    const int fbh = R >> 4, fil = R & 15;
                    float4 val = *(const float4*)(p_s + (fil * 32 + fbh) * PB_STRIDE + po + fk2 * 4);
                    float* dst = attn + (((size_t)(fbh << 10) + ib * TIB + fil) << 10)
                                      + jbase + g * 16 + fk2 * 4;
                    __stcs((float4*)dst, val);
                }
            }

            if (jt + 1 < NTC) {
                const unsigned vd = v_su + (unsigned)(((jt + 1) & 1) * QBUF * 4);
                const int j0n = jbase + (jt + 1) * TJ;
                #pragma unroll
                for (int r = 0; r < 4; r++)
                    CPA16(vd + (unsigned)(r * QS_JJ * 4) + voffB, vsrc + (size_t)(j0n + r) * 64);
                CPCOMMIT();
                CPWAIT1();   // tile jt complete (committed last iteration)
            } else {
                CPWAIT0();
            }

            // issue next tile's scratch loads; consume current (pa, pb)
            float4 na, nb;
            if (jt + 1 < NTC) {
                const float* spn = sbase + ((size_t)(jt + 1) * 512 + tid) * 4;
                na = __ldcs((const float4*)spn);
                nb = __ldcs((const float4*)(spn + 1024));
            }

            float p0v[TJ] = {pa.x * il0, pa.y * il0, pa.z * il0, pa.w * il0};
            float p1v[TJ] = {pb.x * il1, pb.y * il1, pb.z * il1, pb.w * il1};

            const float* vb = v_s + (jt & 1) * QBUF;
            #pragma unroll
            for (int jj = 0; jj < TJ; jj++) {
                float2 p02 = make_float2(p0v[jj], p0v[jj]);
                float2 p12 = make_float2(p1v[jj], p1v[jj]);
                const float* vrow = vb + jj * QS_JJ + bh * QS_BH;
                #pragma unroll
                for (int d4 = 0; d4 < 8; d4++) {
                    float4 V = *(const float4*)(vrow + d4 * 4);
                    float2 vxy = make_float2(V.x, V.y), vzw = make_float2(V.z, V.w);
                    acc0[d4*2]   = f2fma(p02, vxy, acc0[d4*2]);
                    acc0[d4*2+1] = f2fma(p02, vzw, acc0[d4*2+1]);
                    acc1[d4*2]   = f2fma(p12, vxy, acc1[d4*2]);
                    acc1[d4*2+1] = f2fma(p12, vzw, acc1[d4*2+1]);
                }
            }

            if (attn) {
                // stage p into this group's parity half (other parity than any
                // concurrent flush target)
                const int col = ((jt >> 2) & 1) * 16 + (jt & 3) * 4;
                *(float4*)(ps0 + col) = make_float4(p0v[0], p0v[1], p0v[2], p0v[3]);
                *(float4*)(ps1 + col) = make_float4(p1v[0], p1v[1], p1v[2], p1v[3]);
            }

            pa = na; pb = nb;
        }

        // final group flush
        __syncthreads();
        if (attn) {
            const int g = (NTC >> 2) - 1;
            const int po = (g & 1) * 16;
            #pragma unroll
            for (int f = 0; f < 8; f++) {
                const int R  = warp * 64 + f * 8 + frl;
                const int fbh = R >> 4, fil = R & 15;
                float4 val = *(const float4*)(p_s + (fil * 32 + fbh) * PB_STRIDE + po + fk2 * 4);
                float* dst = attn + (((size_t)(fbh << 10) + ib * TIB + fil) << 10)
                                  + jbase + g * 16 + fk2 * 4;
                __stcs((float4*)dst, val);
            }
        }

        float* op0 = g_opart + (((size_t)jbs * 32 + bh) * 1024 + i0) * 32;
        float* op1 = g_opart + (((size_t)jbs * 32 + bh) * 1024 + i1) * 32;
        #pragma unroll
        for (int d4 = 0; d4 < 8; d4++) {
            *(float4*)(op0 + d4 * 4) = make_float4(acc0[d4*2].x,   acc0[d4*2].y,
                                                   acc0[d4*2+1].x, acc0[d4*2+1].y);
            *(float4*)(op1 + d4 * 4) = make_float4(acc1[d4*2].x,   acc1[d4*2].y,
                                                   acc1[d4*2+1].x, acc1[d4*2+1].y);
        }
    }
}

// ============================================================================
// K3: out = sum of JS partial outputs. Also resets g_done for the next launch
// (stream-ordered after k_fused), replacing the serial k0 launch.
// ============================================================================
__global__ __launch_bounds__(256)
void k3_reduce(float* __restrict__ out)
{
    if (blockIdx.x == 0 && threadIdx.x < NIB) g_done[threadIdx.x] = 0;

    const int idx = blockIdx.x * 256 + threadIdx.x;
    const float4* op = (const float4*)g_opart;
    float4 r = op[idx];
    #pragma unroll
    for (int t = 1; t < JS; t++) {
        float4 a = op[idx + (size_t)t * 262144];
        r.x += a.x; r.y += a.y; r.z += a.z; r.w += a.w;
    }
    ((float4*)out)[idx] = r;
}

extern "C" void kernel_launch(void* const* d_in, const int* in_sizes, int n_in,
                              void* d_out, int out_size)
{
    const float *q = 0, *k = 0, *v = 0, *ak = 0;
    int qc = 0;
    for (int idx = 0; idx < n_in; idx++) {
        if (in_sizes[idx] == 33554432) {
            ak = (const float*)d_in[idx];
        } else if (in_sizes[idx] == 1048576) {
            if (qc == 0) q = (const float*)d_in[idx];
            else if (qc == 1) k = (const float*)d_in[idx];
            else if (qc == 2) v = (const float*)d_in[idx];
            qc++;
        }
    }

    const long long OUT_N  = 1048576LL;
    const long long ATTN_N = 33554432LL;
    float* outp  = 0;
    float* attnp = 0;
    long long os = (long long)out_size;
    if (os >= OUT_N + ATTN_N) {           // tuple (out, attn)
        outp  = (float*)d_out;
        attnp = (float*)d_out + OUT_N;
    } else if (os == ATTN_N) {
        attnp = (float*)d_out;
    } else {
        outp = (float*)d_out;
    }

    const int SMEM = SMEM_FLOATS * 4;   // 110,592 B
    cudaFuncSetAttribute(k_fused, cudaFuncAttributeMaxDynamicSharedMemorySize, SMEM);

    // g_done reset: done by k3 at the end of each launch (and static zero-init
    // for the very first). Only attn-only mode (no k3) needs the explicit k0.
    if (!outp)
        k0_zero<<<1, 64>>>();
    k_fused<<<2 * NIB * JS, 256, SMEM>>>(q, k, ak, v, attnp);
    if (outp)
        k3_reduce<<<1024, 256>>>(outp);
}

// round 16
// speedup vs baseline: 1.1455x; 1.1455x over previous
#include <cuda_runtime.h>
#include <math.h>

// Problem constants
#define LSEQ 1024
#define TIB  16           // i-rows per CTA (2 per thread)
#define TJ   4            // j per tile
#define JS   8            // j-splits
#define JCH  (LSEQ/JS)    // 128 j per CTA
#define NTC  (JCH/TJ)     // 32 tiles per CTA
#define NIB  (LSEQ/TIB)   // 64 i-blocks

#define QS_BH 36                 // padded floats per (b,h) row (conflict-free LDS)
#define QS_JJ (32*QS_BH)         // 1152 floats per jj
#define QBUF  (TJ*QS_JJ)         // 4608 floats per q/v buffer
#define AS_JJ 36
#define AS_TI (TJ*AS_JJ+4)       // 148 floats per ti row
#define ABUF  (TIB*AS_TI)        // 2368 floats per a buffer

#define PB_STRIDE 20             // attn staging row stride (16 j + pad)
#define PROWS 512                // 16 i x 32 bh

// dynamic smem: max(k1: 3*QBUF+3*ABUF = 20928, k2: 3*QBUF+PROWS*20 = 24064)
#define SMEM_FLOATS 24064

// Static scratch (allocation-free per harness rules)
__device__ float g_scratch[(size_t)NIB * JS * NTC * 512 * 4];  // p-tilde, 128 MB
__device__ float g_partials[JS * 32768];                       // per-split exp-sums
__device__ float g_opart[(size_t)JS * 32 * 1024 * 32];         // partial PV outputs
__device__ int   g_done[NIB];                                  // k1 completion per ib
__device__ int   g_done2[NIB];                                 // k2 completion per ib

typedef unsigned long long ull;

__device__ __forceinline__ float2 f2mul(float2 a, float2 b) {
    ull ra = *(ull*)&a, rb = *(ull*)&b, rd;
    asm("mul.rn.f32x2 %0, %1, %2;" : "=l"(rd) : "l"(ra), "l"(rb));
    return *(float2*)&rd;
}
__device__ __forceinline__ float2 f2fma(float2 a, float2 b, float2 c) {
    ull ra = *(ull*)&a, rb = *(ull*)&b, rc = *(ull*)&c, rd;
    asm("fma.rn.f32x2 %0, %1, %2, %3;" : "=l"(rd) : "l"(ra), "l"(rb), "l"(rc));
    return *(float2*)&rd;
}
__device__ __forceinline__ float ex2(float x) {
    float r;
    asm("ex2.approx.f32 %0, %1;" : "=f"(r) : "f"(x));
    return r;
}

#define CPA16(dst_u32, src_ptr) \
    asm volatile("cp.async.cg.shared.global [%0], [%1], 16;" :: "r"(dst_u32), "l"(src_ptr))
#define CPCOMMIT() asm volatile("cp.async.commit_group;" ::: "memory")
#define CPWAIT1()  asm volatile("cp.async.wait_group 1;" ::: "memory")
#define CPWAIT0()  asm volatile("cp.async.wait_group 0;" ::: "memory")

// ============================================================================
// k0: counter reset — only needed in attn-only mode (no reduction CTA resets).
// ============================================================================
__global__ void k0_zero()
{
    if (threadIdx.x < NIB) { g_done[threadIdx.x] = 0; g_done2[threadIdx.x] = 0; }
}

// ============================================================================
// Fused launch: bids 0-511 = score chunks (k1), bids 512-1023 = PV chunks (k2).
// Last-finishing PV chunk of each ib also reduces opart -> out (replaces k3)
// and resets that ib's counters for the next graph replay.
// ============================================================================
__global__ __launch_bounds__(256, 2)
void k_fused(const float* __restrict__ q,
             const float* __restrict__ k,
             const float* __restrict__ ak,
             const float* __restrict__ v,
             float* __restrict__ attn,
             float* __restrict__ out)
{
    extern __shared__ float sm[];
    __shared__ int s_lastflag;
    const int bid = blockIdx.x;
    const int tid = threadIdx.x;
    const int lane = tid & 31, warp = tid >> 5;
    const int ti = lane >> 2;
    const int bh = warp * 4 + (lane & 3);

    if (bid < NIB * JS) {
        // ==================== SCORE CHUNK (k1, R14-proven) ====================
        const int ib  = bid >> 3;
        const int jbs = bid & 7;
        const int b = bh >> 3, h = bh & 7;
        const int i0 = ib * TIB + ti, i1 = i0 + 8;
        const int jbase = jbs * JCH;

        float* q_s = sm;                 // [3][QBUF]
        float* a_s = sm + 3 * QBUF;      // [3][ABUF]
        const unsigned q_su = (unsigned)__cvta_generic_to_shared(q_s);
        const unsigned a_su = (unsigned)__cvta_generic_to_shared(a_s);

        const float SC = 0.17677669529663687f * 1.4426950408889634f;
        float2 kr0[16], kr1[16];
        {
            const float4* kp0 = (const float4*)(k + ((size_t)(b * LSEQ + i0)) * 256 + h * 32);
            const float4* kp1 = (const float4*)(k + ((size_t)(b * LSEQ + i1)) * 256 + h * 32);
            #pragma unroll
            for (int d4 = 0; d4 < 8; d4++) {
                float4 t0 = kp0[d4], t1 = kp1[d4];
                kr0[d4*2]   = make_float2(t0.x * SC, t0.y * SC);
                kr0[d4*2+1] = make_float2(t0.z * SC, t0.w * SC);
                kr1[d4*2]   = make_float2(t1.x * SC, t1.y * SC);
                kr1[d4*2+1] = make_float2(t1.z * SC, t1.w * SC);
            }
        }

        const int qbb = tid >> 6, c4 = tid & 63;
        const unsigned qoffB = (unsigned)(((qbb * 8 + (c4 >> 3)) * QS_BH + (c4 & 7) * 4) * 4);
        const float4* qsrc = (const float4*)q + (size_t)qbb * (LSEQ * 64) + c4;
        const int ati = tid >> 5, ajj = (tid >> 3) & 3, ad4 = tid & 7;
        const unsigned aoff0B = (unsigned)((ati * AS_TI + ajj * AS_JJ + ad4 * 4) * 4);
        const unsigned aoff1B = aoff0B + (unsigned)(8 * AS_TI * 4);
        const float4* asrc0 = (const float4*)ak + ((size_t)(ib * TIB + ati)) * (LSEQ * 8) + ad4;
        const float4* asrc1 = asrc0 + (size_t)8 * (LSEQ * 8);

        #pragma unroll
        for (int t = 0; t < 2; t++) {
            const int j0 = jbase + t * TJ;
            const unsigned qd = q_su + (unsigned)(t * QBUF * 4);
            const unsigned ad = a_su + (unsigned)(t * ABUF * 4);
            #pragma unroll
            for (int r = 0; r < 4; r++)
                CPA16(qd + (unsigned)(r * QS_JJ * 4) + qoffB, qsrc + (size_t)(j0 + r) * 64);
            CPA16(ad + aoff0B, asrc0 + (size_t)(j0 + ajj) * 8);
            CPA16(ad + aoff1B, asrc1 + (size_t)(j0 + ajj) * 8);
            CPCOMMIT();
        }

        float l0 = 0.f, l1 = 0.f;
        float* sbase = g_scratch + (size_t)(ib * JS + jbs) * (NTC * 2048);

        int cur = 0;
        for (int jt = 0; jt < NTC; jt++) {
            CPWAIT1();
            __syncthreads();

            if (jt + 2 < NTC) {
                int sbuf = cur + 2; if (sbuf >= 3) sbuf -= 3;
                const int j0n = jbase + (jt + 2) * TJ;
                const unsigned qd = q_su + (unsigned)(sbuf * QBUF * 4);
                const unsigned ad = a_su + (unsigned)(sbuf * ABUF * 4);
                #pragma unroll
                for (int r = 0; r < 4; r++)
                    CPA16(qd + (unsigned)(r * QS_JJ * 4) + qoffB, qsrc + (size_t)(j0n + r) * 64);
                CPA16(ad + aoff0B, asrc0 + (size_t)(j0n + ajj) * 8);
                CPA16(ad + aoff1B, asrc1 + (size_t)(j0n + ajj) * 8);
                CPCOMMIT();
            }

            const float* qb = q_s + cur * QBUF;
            const float* ab = a_s + cur * ABUF;
            float e4a[TJ], e4b[TJ];

            #pragma unroll
            for (int jj = 0; jj < TJ; jj++) {
                const float* qrow = qb + jj * QS_JJ + bh * QS_BH;
                const float* ar0  = ab + ti * AS_TI + jj * AS_JJ;
                const float* ar1  = ar0 + 8 * AS_TI;
                float2 a00 = make_float2(0.f,0.f), a01 = a00, a10 = a00, a11 = a00;
                #pragma unroll
                for (int d4 = 0; d4 < 8; d4++) {
                    float4 Q  = *(const float4*)(qrow + d4 * 4);
                    float4 A0 = *(const float4*)(ar0  + d4 * 4);
                    float4 A1 = *(const float4*)(ar1  + d4 * 4);
                    float2 qxy = make_float2(Q.x, Q.y), qzw = make_float2(Q.z, Q.w);
                    a00 = f2fma(f2mul(make_float2(A0.x, A0.y), qxy), kr0[d4*2],   a00);
                    a01 = f2fma(f2mul(make_float2(A0.z, A0.w), qzw), kr0[d4*2+1], a01);
                    a10 = f2fma(f2mul(make_float2(A1.x, A1.y), qxy), kr1[d4*2],   a10);
                    a11 = f2fma(f2mul(make_float2(A1.z, A1.w), qzw), kr1[d4*2+1], a11);
                }
                float e0 = ex2((a00.x + a00.y) + (a01.x + a01.y));
                float e1 = ex2((a10.x + a10.y) + (a11.x + a11.y));
                e4a[jj] = e0; l0 += e0;
                e4b[jj] = e1; l1 += e1;
            }

            float* sp = sbase + ((size_t)jt * 512 + tid) * 4;
            __stcs((float4*)sp,          make_float4(e4a[0], e4a[1], e4a[2], e4a[3]));
            __stcs((float4*)(sp + 1024), make_float4(e4b[0], e4b[1], e4b[2], e4b[3]));

            cur = (cur + 1 == 3) ? 0 : cur + 1;
        }

        g_partials[jbs * 32768 + bh * 1024 + i0] = l0;
        g_partials[jbs * 32768 + bh * 1024 + i1] = l1;

        __syncthreads();
        if (tid == 0) {
            __threadfence();
            asm volatile("red.release.gpu.global.add.s32 [%0], 1;"
                         :: "l"(&g_done[ib]) : "memory");
        }

    } else {
        // ==================== PV CHUNK (k2, R14-proven) ====================
        const int c   = bid - NIB * JS;
        const int ib  = c >> 3;
        const int jbs = c & 7;
        const int i0 = ib * TIB + ti, i1 = i0 + 8;
        const int jbase = jbs * JCH;
        const int row0 = bh * 1024 + i0, row1 = bh * 1024 + i1;

        float* v_s = sm;                 // [3][QBUF]
        float* p_s = sm + 3 * QBUF;      // [512][PB_STRIDE]
        const unsigned v_su = (unsigned)__cvta_generic_to_shared(v_s);

        const int vbb = tid >> 6, c4 = tid & 63;
        const unsigned voffB = (unsigned)(((vbb * 8 + (c4 >> 3)) * QS_BH + (c4 & 7) * 4) * 4);
        const float4* vsrc = (const float4*)v + (size_t)vbb * (LSEQ * 64) + c4;

        // V prologue BEFORE the spin (independent of k1)
        #pragma unroll
        for (int t = 0; t < 2; t++) {
            const int j0 = jbase + t * TJ;
            const unsigned vd = v_su + (unsigned)(t * QBUF * 4);
            #pragma unroll
            for (int r = 0; r < 4; r++)
                CPA16(vd + (unsigned)(r * QS_JJ * 4) + voffB, vsrc + (size_t)(j0 + r) * 64);
            CPCOMMIT();
        }

        // acquire-spin: all 8 score chunks of this ib must be done
        if (tid == 0) {
            int val;
            do {
                asm volatile("ld.global.acquire.gpu.b32 %0, [%1];"
                             : "=r"(val) : "l"(&g_done[ib]) : "memory");
                if (val < JS) __nanosleep(256);
            } while (val < JS);
        }
        __syncthreads();

        float gl0 = 0.f, gl1 = 0.f;
        #pragma unroll
        for (int t = 0; t < JS; t++) {
            gl0 += g_partials[t * 32768 + row0];
            gl1 += g_partials[t * 32768 + row1];
        }
        const float il0 = 1.0f / gl0, il1 = 1.0f / gl1;

        const float* sbase = g_scratch + (size_t)(ib * JS + jbs) * (NTC * 2048);

        float4 pa = __ldcs((const float4*)(sbase + (size_t)tid * 4));
        float4 pb = __ldcs((const float4*)(sbase + (size_t)tid * 4 + 1024));

        float* ps0 = p_s + (ti * 32 + bh) * PB_STRIDE;
        float* ps1 = p_s + ((ti + 8) * 32 + bh) * PB_STRIDE;
        const int frl = lane >> 2, fk2 = lane & 3;

        float2 acc0[16], acc1[16];
        #pragma unroll
        for (int r = 0; r < 16; r++) { acc0[r] = make_float2(0.f,0.f); acc1[r] = acc0[r]; }

        int cur = 0;
        for (int jt = 0; jt < NTC; jt++) {
            __syncthreads();
            if (jt + 2 < NTC) {
                int sbuf = cur + 2; if (sbuf >= 3) sbuf -= 3;
                const int j0n = jbase + (jt + 2) * TJ;
                const unsigned vd = v_su + (unsigned)(sbuf * QBUF * 4);
                #pragma unroll
                for (int r = 0; r < 4; r++)
                    CPA16(vd + (unsigned)(r * QS_JJ * 4) + voffB, vsrc + (size_t)(j0n + r) * 64);
                CPCOMMIT();
            }
            if (jt + 1 < NTC) CPWAIT1(); else CPWAIT0();
            __syncthreads();

            float4 na, nb;
            if (jt + 1 < NTC) {
                const float* spn = sbase + ((size_t)(jt + 1) * 512 + tid) * 4;
                na = __ldcs((const float4*)spn);
                nb = __ldcs((const float4*)(spn + 1024));
            }

            float p0v[TJ] = {pa.x * il0, pa.y * il0, pa.z * il0, pa.w * il0};
            float p1v[TJ] = {pb.x * il1, pb.y * il1, pb.z * il1, pb.w * il1};

            const float* vb = v_s + cur * QBUF;
            #pragma unroll
            for (int jj = 0; jj < TJ; jj++) {
                float2 p02 = make_float2(p0v[jj], p0v[jj]);
                float2 p12 = make_float2(p1v[jj], p1v[jj]);
                const float* vrow = vb + jj * QS_JJ + bh * QS_BH;
                #pragma unroll
                for (int d4 = 0; d4 < 8; d4++) {
                    float4 V = *(const float4*)(vrow + d4 * 4);
                    float2 vxy = make_float2(V.x, V.y), vzw = make_float2(V.z, V.w);
                    acc0[d4*2]   = f2fma(p02, vxy, acc0[d4*2]);
                    acc0[d4*2+1] = f2fma(p02, vzw, acc0[d4*2+1]);
                    acc1[d4*2]   = f2fma(p12, vxy, acc1[d4*2]);
                    acc1[d4*2+1] = f2fma(p12, vzw, acc1[d4*2+1]);
                }
            }

            if (attn) {
                const int col = (jt & 3) * 4;
                *(float4*)(ps0 + col) = make_float4(p0v[0], p0v[1], p0v[2], p0v[3]);
                *(float4*)(ps1 + col) = make_float4(p1v[0], p1v[1], p1v[2], p1v[3]);

                if ((jt & 3) == 3) {
                    __syncthreads();
                    const int g = jt >> 2;
                    #pragma unroll
                    for (int f = 0; f < 8; f++) {
                        const int R  = warp * 64 + f * 8 + frl;
                        const int fbh = R >> 4, fil = R & 15;
                        float4 val = *(const float4*)(p_s + (fil * 32 + fbh) * PB_STRIDE + fk2 * 4);
                        float* dst = attn + (((size_t)(fbh << 10) + ib * TIB + fil) << 10)
                                          + jbase + g * 16 + fk2 * 4;
                        __stcs((float4*)dst, val);
                    }
                }
            }

            pa = na; pb = nb;
            cur = (cur + 1 == 3) ? 0 : cur + 1;
        }

        float* op0 = g_opart + (((size_t)jbs * 32 + bh) * 1024 + i0) * 32;
        float* op1 = g_opart + (((size_t)jbs * 32 + bh) * 1024 + i1) * 32;
        #pragma unroll
        for (int d4 = 0; d4 < 8; d4++) {
            *(float4*)(op0 + d4 * 4) = make_float4(acc0[d4*2].x,   acc0[d4*2].y,
                                                   acc0[d4*2+1].x, acc0[d4*2+1].y);
            *(float4*)(op1 + d4 * 4) = make_float4(acc1[d4*2].x,   acc1[d4*2].y,
                                                   acc1[d4*2+1].x, acc1[d4*2+1].y);
        }

        // ===== inline reduction (replaces k3): last PV chunk of ib sums =====
        if (out) {
            __syncthreads();                // all opart stores executed
            if (tid == 0) {
                __threadfence();            // publish CTA's opart at gpu scope
                int old = atomicAdd(&g_done2[ib], 1);
                s_lastflag = (old == JS - 1);
            }
            __syncthreads();
            if (s_lastflag) {
                __threadfence();            // acquire: see all 8 chunks' opart
                // reduce this ib's 16 rows: 4096 float4 = 256 thr x 16
                const float4* op = (const float4*)g_opart;
                #pragma unroll
                for (int r = 0; r < 16; r++) {
                    const int idx2 = tid + r * 256;          // 0..4095
                    const int rbh = idx2 >> 7;               // 32 bh
                    const int rem = idx2 & 127;              // 16 il x 8 d4
                    const int ril = rem >> 3, rd4 = rem & 7;
                    const size_t base = ((size_t)(rbh << 10) + ib * TIB + ril) * 8 + rd4;
                    float4 s = op[base];
                    #pragma unroll
                    for (int t = 1; t < JS; t++) {
                        float4 a2 = op[base + (size_t)t * 262144];
                        s.x += a2.x; s.y += a2.y; s.z += a2.z; s.w += a2.w;
                    }
                    ((float4*)out)[base] = s;
                }
                // reset counters for next graph replay
                if (tid == 0) { g_done[ib] = 0; g_done2[ib] = 0; }
            }
        }
    }
}

extern "C" void kernel_launch(void* const* d_in, const int* in_sizes, int n_in,
                              void* d_out, int out_size)
{
    const float *q = 0, *k = 0, *v = 0, *ak = 0;
    int qc = 0;
    for (int idx = 0; idx < n_in; idx++) {
        if (in_sizes[idx] == 33554432) {
            ak = (const float*)d_in[idx];
        } else if (in_sizes[idx] == 1048576) {
            if (qc == 0) q = (const float*)d_in[idx];
            else if (qc == 1) k = (const float*)d_in[idx];
            else if (qc == 2) v = (const float*)d_in[idx];
            qc++;
        }
    }

    const long long OUT_N  = 1048576LL;
    const long long ATTN_N = 33554432LL;
    float* outp  = 0;
    float* attnp = 0;
    long long os = (long long)out_size;
    if (os >= OUT_N + ATTN_N) {           // tuple (out, attn)
        outp  = (float*)d_out;
        attnp = (float*)d_out + OUT_N;
    } else if (os == ATTN_N) {
        attnp = (float*)d_out;
    } else {
        outp = (float*)d_out;
    }

    const int SMEM = SMEM_FLOATS * 4;   // 96,256 B
    cudaFuncSetAttribute(k_fused, cudaFuncAttributeMaxDynamicSharedMemorySize, SMEM);

    // In out/tuple mode the reducing CTAs reset the counters; attn-only mode
    // has no reducers, so reset explicitly.
    if (!outp)
        k0_zero<<<1, 64>>>();
    k_fused<<<2 * NIB * JS, 256, SMEM>>>(q, k, ak, v, attnp, outp);
}